// round 15
// baseline (speedup 1.0000x reference)
#include <cuda_runtime.h>
#include <cmath>
#include <complex>
#include <algorithm>

// ---------------- device scratch (static; no allocation allowed) ----------------
__device__ float  g_res[262144];    // segment sums res_sph [G*9], zeroed per launch
__device__ float4 g_W0q[32 * 32];   // packed irrep-0 weights: [u/4][lane] = rows (u..u+3)
__device__ float4 g_W1q[16 * 32];   // packed irrep-1 weights
__device__ float4 g_W2q[8 * 32];    // packed irrep-2 weights
__device__ float4 g_Wg1p[64 * 32];  // packed gate1: [i/2][lane] = (W[i][2l],W[i][2l+1],W[i+1][2l],W[i+1][2l+1])
__device__ float2 g_We[32 * 16];    // packed gate2 tail col: [i/2][c] = (Wg2[i][128+c], Wg2[i+1][128+c])

// ---------------- param structs (host-computed constants) ----------------
struct TPParams {
    float tab[357];   // dense W3J tables, packed in INS order
    float ck[9];      // sqrt((2*l3+1)/16)/sqrt(len_l3) per instruction
};
struct FinParams {
    float M[81];      // M[k*9 + a*3 + b] = Q_COB[k][CART[a]][CART[b]]
};

// table offsets (must match host packing order)
#define OFF_K0 0
#define OFF_K1 1
#define OFF_K2 26
#define OFF_K3 35
#define OFF_K4 62
#define OFF_K5 107
#define OFF_K6 132
#define OFF_K7 157
#define OFF_K8 232

#define NB   2      // nodes per warp (reduced: fits 64-reg cap for 4 blocks/SM)
#define WPB  8      // warps per block (256 threads -> 4 blocks/SM = 32 warps)
#define TPB  (WPB*32)
#define NPB  (NB*WPB)
#define NS   608    // floats of scratch per node (overlaid, h in registers)

// per-node scratch layout (floats):
//  [0,128)   x_scalar      (silu hidden overlays [0,64) after gate1)
//  [128,256) p0            (w[144] overlays [128,272) after irreps+gate1)
//  [256,448) p1 transposed [3][64]
//  [448,608) p2 transposed [5][32]
#define O_W   128
#define O_P0  128
#define O_P1  256
#define O_P2  448

// ---------------- prep: zero segments + build packed weights ----------------
__global__ void prep_kernel(const float* __restrict__ WU0, const float* __restrict__ WU1,
                            const float* __restrict__ WU2, const float* __restrict__ WV0,
                            const float* __restrict__ WV1, const float* __restrict__ WV2,
                            const float* __restrict__ Wg1, const float* __restrict__ Wg2,
                            int g9) {
    int t = blockIdx.x * blockDim.x + threadIdx.x;
    if (t < g9) g_res[t] = 0.f;
    if (t < 32 * 32) {  // irrep-0: rows 4k..4k+3, column c
        int k = t >> 5, c = t & 31;
        float w[4];
#pragma unroll
        for (int r = 0; r < 4; r++)
            w[r] = (c < 16) ? WU0[(4 * k + r) * 16 + c] : WV0[(4 * k + r) * 16 + c - 16];
        g_W0q[t] = make_float4(w[0], w[1], w[2], w[3]);
    }
    if (t < 16 * 32) {
        int k = t >> 5, c = t & 31;
        float w[4];
#pragma unroll
        for (int r = 0; r < 4; r++)
            w[r] = (c < 16) ? WU1[(4 * k + r) * 16 + c] : WV1[(4 * k + r) * 16 + c - 16];
        g_W1q[t] = make_float4(w[0], w[1], w[2], w[3]);
    }
    if (t < 8 * 32) {
        int k = t >> 5, c = t & 31;
        float w[4];
#pragma unroll
        for (int r = 0; r < 4; r++)
            w[r] = (c < 16) ? WU2[(4 * k + r) * 16 + c] : WV2[(4 * k + r) * 16 + c - 16];
        g_W2q[t] = make_float4(w[0], w[1], w[2], w[3]);
    }
    if (t < 64 * 32) {  // gate1 packed: rows 2k,2k+1 x cols 2c,2c+1
        int k = t >> 5, c = t & 31;
        g_Wg1p[t] = make_float4(Wg1[(2 * k) * 64 + 2 * c],     Wg1[(2 * k) * 64 + 2 * c + 1],
                                Wg1[(2 * k + 1) * 64 + 2 * c], Wg1[(2 * k + 1) * 64 + 2 * c + 1]);
    }
    if (t < 32 * 16) {  // gate2 tail col packed: rows 2k,2k+1, col 128+c
        int k = t >> 4, c = t & 15;
        g_We[t] = make_float2(Wg2[(2 * k) * 144 + 128 + c], Wg2[(2 * k + 1) * 144 + 128 + c]);
    }
}

__global__ void fin_kernel(float* __restrict__ out, int G, FinParams F) {
    int t = blockIdx.x * blockDim.x + threadIdx.x;
    if (t >= G * 9) return;
    int g = t / 9, ab = t - g * 9;
    const float* r = g_res + g * 9;
    float s = 0.f;
#pragma unroll
    for (int k = 0; k < 9; k++) s = fmaf(r[k], F.M[k * 9 + ab], s);
    out[t] = s;
}

// ---------------- real-basis W3J sparsity predicate (compile-time) ----------------
__host__ __device__ constexpr bool w3j_nz(int l1, int i, int l2, int j, int l3, int m) {
    int m1 = i - l1, m2 = j - l2, m3 = m - l3;
    int a1 = m1 < 0 ? -m1 : m1, a2 = m2 < 0 ? -m2 : m2, a3 = m3 < 0 ? -m3 : m3;
    int d = a1 > a2 ? a1 - a2 : a2 - a1;
    bool mag = (a3 == a1 + a2) || (a3 == d);
    int negs = (m1 < 0 ? 1 : 0) + (m2 < 0 ? 1 : 0) + (m3 < 0 ? 1 : 0);
    return mag && ((negs & 1) == ((l1 + l2 + l3) & 1));
}

// ---------------- sparse tensor-product contraction ----------------
template <int L1, int L2, int L3>
__device__ __forceinline__ void tpc_sp(const float* __restrict__ T, float s,
                                       const float* a, const float* b, float* acc) {
    constexpr int D1 = 2 * L1 + 1, D2 = 2 * L2 + 1, D3 = 2 * L3 + 1;
#pragma unroll
    for (int i = 0; i < D1; i++) {
        float as = a[i] * s;
#pragma unroll
        for (int j = 0; j < D2; j++) {
            float ab = as * b[j];
#pragma unroll
            for (int m = 0; m < D3; m++) {
                if (w3j_nz(L1, i, L2, j, L3, m))
                    acc[m] = fmaf(ab, T[(i * D2 + j) * D3 + m], acc[m]);
            }
        }
    }
}

__device__ __forceinline__ float sel4(const float4& v, int t) {
    return (t == 0) ? v.x : (t == 1) ? v.y : (t == 2) ? v.z : v.w;
}

// =====================================================================
// main fused kernel: one warp per NB nodes; h kept in registers
// =====================================================================
__global__ void __launch_bounds__(TPB, 4) tp_main(
    const int* __restrict__ batch,
    const float* __restrict__ xs, const float* __restrict__ xsph,
    const float* __restrict__ bg1,
    const float* __restrict__ Wg2, const float* __restrict__ bg2,
    const float* __restrict__ Wp0, const float* __restrict__ Wp1, const float* __restrict__ Wp2,
    int N, TPParams P) {
    extern __shared__ __align__(16) float dyn[];
    float* s_tab = dyn;          // 357 (+3 pad)
    float* s_cf  = dyn + 360;    // 9 (+3 pad)
    float* scratch = dyn + 372;  // NPB * NS

    for (int i = threadIdx.x; i < 357; i += TPB) s_tab[i] = P.tab[i];
    if (threadIdx.x < 9) {
        int k = threadIdx.x;
        float wp;
        switch (k) {
            case 0: wp = __ldg(Wp0 + 0); break;   // (0,0,0)
            case 1: wp = __ldg(Wp2 + 0); break;   // (0,2,2)
            case 2: wp = __ldg(Wp0 + 1); break;   // (1,1,0)
            case 3: wp = __ldg(Wp1 + 0); break;   // (1,1,1)
            case 4: wp = __ldg(Wp2 + 1); break;   // (1,1,2)
            case 5: wp = __ldg(Wp2 + 2); break;   // (2,0,2)
            case 6: wp = __ldg(Wp0 + 2); break;   // (2,2,0)
            case 7: wp = __ldg(Wp1 + 1); break;   // (2,2,1)
            default: wp = __ldg(Wp2 + 3); break;  // (2,2,2)
        }
        s_cf[k] = P.ck[k] * wp;
    }
    __syncthreads();

    const int warp = threadIdx.x >> 5;
    const int lane = threadIdx.x & 31;
    const int n0 = blockIdx.x * NPB + warp * NB;
    float* S0 = scratch + (size_t)(warp * NB) * NS;
    float* S1 = S0 + NS;

    // ---- stage node inputs (all float4 LDG; p1/p2 scatter-transposed to shared) ----
#pragma unroll
    for (int j = 0; j < NB; j++) {
        int n = n0 + j;
        float* Sx = S0 + j * NS;
        if (n < N) {
            const float4* xv = (const float4*)(xs + (size_t)n * 128);
            ((float4*)Sx)[lane] = __ldg(xv + lane);
            const float4* p0v = (const float4*)(xsph + (size_t)n * 480);
            ((float4*)(Sx + O_P0))[lane] = __ldg(p0v + lane);
            const float4* prv = (const float4*)(xsph + (size_t)n * 480 + 128);  // 88 float4
#pragma unroll
            for (int r = 0; r < 3; r++) {
                int q = lane + 32 * r;
                if (q < 88) {
                    float4 v = __ldg(prv + q);
                    int base = 4 * q;
#pragma unroll
                    for (int t = 0; t < 4; t++) {
                        int idx = base + t;
                        float val = sel4(v, t);
                        if (idx < 192) {
                            int u = idx / 3, i = idx - 3 * u;
                            Sx[O_P1 + i * 64 + u] = val;
                        } else {
                            int kk = idx - 192;
                            int u = kk / 5, i = kk - 5 * u;
                            Sx[O_P2 + i * 32 + u] = val;
                        }
                    }
                }
            }
        } else {
#pragma unroll
            for (int r = 0; r < 19; r++) {
                int idx = lane + 32 * r;
                if (idx < 608) Sx[idx] = 0.f;
            }
        }
    }
    __syncwarp();

    // ---- irrep linears FIRST: results stay in registers ----
    float h0[NB];
    float h1[NB][3];
    float h2[NB][5];
    {
        {   // l = 0  (inputs at O_P0); packed weights: 4 rows per LDG.128
            float s[NB] = {0.f, 0.f};
#pragma unroll 2
            for (int u = 0; u < 128; u += 4) {
                float4 p0 = *(const float4*)(S0 + O_P0 + u);
                float4 p1 = *(const float4*)(S1 + O_P0 + u);
                float4 w = __ldg(g_W0q + (u >> 2) * 32 + lane);
                s[0] = fmaf(p0.x, w.x, s[0]); s[0] = fmaf(p0.y, w.y, s[0]);
                s[0] = fmaf(p0.z, w.z, s[0]); s[0] = fmaf(p0.w, w.w, s[0]);
                s[1] = fmaf(p1.x, w.x, s[1]); s[1] = fmaf(p1.y, w.y, s[1]);
                s[1] = fmaf(p1.z, w.z, s[1]); s[1] = fmaf(p1.w, w.w, s[1]);
            }
            const float C0 = 0.08838834764831845f;  // 1/sqrt(128)
#pragma unroll
            for (int j = 0; j < NB; j++) h0[j] = s[j] * C0;
        }
        {   // l = 1  (inputs transposed [3][64] at O_P1); 4 rows per iter, component-outer
            float b[NB][3];
#pragma unroll
            for (int j = 0; j < NB; j++) { b[j][0] = 0.f; b[j][1] = 0.f; b[j][2] = 0.f; }
#pragma unroll 2
            for (int u = 0; u < 64; u += 4) {
                float4 w = __ldg(g_W1q + (u >> 2) * 32 + lane);
#pragma unroll
                for (int i = 0; i < 3; i++) {
                    float4 q0 = *(const float4*)(S0 + O_P1 + i * 64 + u);
                    float4 q1 = *(const float4*)(S1 + O_P1 + i * 64 + u);
                    b[0][i] = fmaf(q0.x, w.x, b[0][i]); b[0][i] = fmaf(q0.y, w.y, b[0][i]);
                    b[0][i] = fmaf(q0.z, w.z, b[0][i]); b[0][i] = fmaf(q0.w, w.w, b[0][i]);
                    b[1][i] = fmaf(q1.x, w.x, b[1][i]); b[1][i] = fmaf(q1.y, w.y, b[1][i]);
                    b[1][i] = fmaf(q1.z, w.z, b[1][i]); b[1][i] = fmaf(q1.w, w.w, b[1][i]);
                }
            }
#pragma unroll
            for (int j = 0; j < NB; j++)
#pragma unroll
                for (int i = 0; i < 3; i++) h1[j][i] = b[j][i] * 0.125f;
        }
        {   // l = 2  (inputs transposed [5][32] at O_P2); 4 rows per iter, component-outer
            float d[NB][5];
#pragma unroll
            for (int j = 0; j < NB; j++)
#pragma unroll
                for (int i = 0; i < 5; i++) d[j][i] = 0.f;
#pragma unroll 2
            for (int u = 0; u < 32; u += 4) {
                float4 w = __ldg(g_W2q + (u >> 2) * 32 + lane);
#pragma unroll
                for (int i = 0; i < 5; i++) {
                    float4 r0 = *(const float4*)(S0 + O_P2 + i * 32 + u);
                    float4 r1 = *(const float4*)(S1 + O_P2 + i * 32 + u);
                    d[0][i] = fmaf(r0.x, w.x, d[0][i]); d[0][i] = fmaf(r0.y, w.y, d[0][i]);
                    d[0][i] = fmaf(r0.z, w.z, d[0][i]); d[0][i] = fmaf(r0.w, w.w, d[0][i]);
                    d[1][i] = fmaf(r1.x, w.x, d[1][i]); d[1][i] = fmaf(r1.y, w.y, d[1][i]);
                    d[1][i] = fmaf(r1.z, w.z, d[1][i]); d[1][i] = fmaf(r1.w, w.w, d[1][i]);
                }
            }
            const float C2 = 0.17677669529663687f;  // 1/sqrt(32)
#pragma unroll
            for (int j = 0; j < NB; j++)
#pragma unroll
                for (int i = 0; i < 5; i++) h2[j][i] = d[j][i] * C2;
        }
    }
    __syncwarp();

    // ---- gate layer 1: hidden = silu(x @ Wg1 + bg1); packed weights (2 rows/LDG.128) ----
    {
        float b0 = __ldg(bg1 + 2 * lane), b1 = __ldg(bg1 + 2 * lane + 1);
        float a00 = b0, a01 = b1, a10 = b0, a11 = b1;
#pragma unroll 2
        for (int i = 0; i < 128; i += 4) {
            float4 x0 = *(const float4*)(S0 + i);
            float4 x1 = *(const float4*)(S1 + i);
            float4 wa = __ldg(g_Wg1p + (i >> 1) * 32 + lane);        // rows i, i+1
            float4 wb = __ldg(g_Wg1p + ((i >> 1) + 1) * 32 + lane);  // rows i+2, i+3
            a00 = fmaf(x0.x, wa.x, a00); a01 = fmaf(x0.x, wa.y, a01);
            a00 = fmaf(x0.y, wa.z, a00); a01 = fmaf(x0.y, wa.w, a01);
            a00 = fmaf(x0.z, wb.x, a00); a01 = fmaf(x0.z, wb.y, a01);
            a00 = fmaf(x0.w, wb.z, a00); a01 = fmaf(x0.w, wb.w, a01);
            a10 = fmaf(x1.x, wa.x, a10); a11 = fmaf(x1.x, wa.y, a11);
            a10 = fmaf(x1.y, wa.z, a10); a11 = fmaf(x1.y, wa.w, a11);
            a10 = fmaf(x1.z, wb.x, a10); a11 = fmaf(x1.z, wb.y, a11);
            a10 = fmaf(x1.w, wb.z, a10); a11 = fmaf(x1.w, wb.w, a11);
        }
        S0[2 * lane] = a00 / (1.f + __expf(-a00));
        S0[2 * lane + 1] = a01 / (1.f + __expf(-a01));
        S1[2 * lane] = a10 / (1.f + __expf(-a10));
        S1[2 * lane + 1] = a11 / (1.f + __expf(-a11));
    }
    __syncwarp();

    // ---- gate layer 2: w = hidden @ Wg2 + bg2; w -> [128,272) (p dead) ----
    {
        float c0[4], c1[4];
#pragma unroll
        for (int t = 0; t < 4; t++) {
            float b = __ldg(bg2 + 4 * lane + t);
            c0[t] = b; c1[t] = b;
        }
        float eb = __ldg(bg2 + 128 + (lane & 15));
        float e0 = eb, e1 = eb;
#pragma unroll 4
        for (int i = 0; i < 64; i += 2) {
            float2 g0 = *(const float2*)(S0 + i);
            float2 g1 = *(const float2*)(S1 + i);
            float2 wep = __ldg(g_We + (i >> 1) * 16 + (lane & 15));  // tail col rows i, i+1
#pragma unroll
            for (int t = 0; t < 2; t++) {
                const float* wrow = Wg2 + (i + t) * 144;
                float4 wv = __ldg((const float4*)wrow + lane);
                float we = t ? wep.y : wep.x;
                float v0 = t ? g0.y : g0.x;
                float v1 = t ? g1.y : g1.x;
                c0[0] = fmaf(v0, wv.x, c0[0]); c0[1] = fmaf(v0, wv.y, c0[1]);
                c0[2] = fmaf(v0, wv.z, c0[2]); c0[3] = fmaf(v0, wv.w, c0[3]);
                c1[0] = fmaf(v1, wv.x, c1[0]); c1[1] = fmaf(v1, wv.y, c1[1]);
                c1[2] = fmaf(v1, wv.z, c1[2]); c1[3] = fmaf(v1, wv.w, c1[3]);
                e0 = fmaf(v0, we, e0); e1 = fmaf(v1, we, e1);
            }
        }
#pragma unroll
        for (int t = 0; t < 4; t++) {
            S0[O_W + 4 * lane + t] = c0[t];
            S1[O_W + 4 * lane + t] = c1[t];
        }
        if (lane < 16) {
            S0[O_W + 128 + lane] = e0;
            S1[O_W + 128 + lane] = e1;
        }
    }
    __syncwarp();

    // ---- tensor product per node; h via shfl; batch-uniform merged reduction ----
    const int u = lane & 15, half = lane >> 4;
    int bfirst = __ldg(batch + (n0 < N ? n0 : N - 1));
    bool uni = (n0 + NB <= N) && (__ldg(batch + n0 + NB - 1) == bfirst);

    float TA[9] = {0, 0, 0, 0, 0, 0, 0, 0, 0};
#pragma unroll 1
    for (int j = 0; j < NB; j++) {
        const float* Sw = S0 + j * NS + O_W;
        // hoist per-node gate weights (LDS) BEFORE the serial shfl chain
        float w1, w2, w3, w4, w5;
        if (half == 0) {
            w1 = Sw[16 + u] * s_cf[1];
            w2 = Sw[64 + u] * s_cf[4];
            w3 = Sw[80 + u] * s_cf[5];
            w4 = Sw[96 + u] * s_cf[6];
            w5 = Sw[112 + u] * s_cf[7];
        } else {
            w1 = Sw[u] * s_cf[0];
            w2 = Sw[32 + u] * s_cf[2];
            w3 = Sw[48 + u] * s_cf[3];
            w4 = Sw[128 + u] * s_cf[8];
            w5 = 0.f;
        }

        float own[9], par[9];
        own[0] = h0[j];
#pragma unroll
        for (int i = 0; i < 3; i++) own[1 + i] = h1[j][i];
#pragma unroll
        for (int i = 0; i < 5; i++) own[4 + i] = h2[j][i];
#pragma unroll
        for (int i = 0; i < 9; i++) par[i] = __shfl_xor_sync(0xffffffffu, own[i], 16);
        float hu0 = half ? par[0] : own[0];
        float hv0 = half ? own[0] : par[0];
        float hu1[3], hv1[3], hu2[5], hv2[5];
#pragma unroll
        for (int i = 0; i < 3; i++) {
            hu1[i] = half ? par[1 + i] : own[1 + i];
            hv1[i] = half ? own[1 + i] : par[1 + i];
        }
#pragma unroll
        for (int i = 0; i < 5; i++) {
            hu2[i] = half ? par[4 + i] : own[4 + i];
            hv2[i] = half ? own[4 + i] : par[4 + i];
        }

        float A[9] = {0, 0, 0, 0, 0, 0, 0, 0, 0};
        if (half == 0) {
            tpc_sp<0, 2, 2>(s_tab + OFF_K1, w1, &hu0, hv2, A + 4);   // (0,2,2)
            tpc_sp<1, 1, 2>(s_tab + OFF_K4, w2, hu1, hv1, A + 4);    // (1,1,2)
            tpc_sp<2, 0, 2>(s_tab + OFF_K5, w3, hu2, &hv0, A + 4);   // (2,0,2)
            tpc_sp<2, 2, 0>(s_tab + OFF_K6, w4, hu2, hv2, A + 0);    // (2,2,0)
            tpc_sp<2, 2, 1>(s_tab + OFF_K7, w5, hu2, hv2, A + 1);    // (2,2,1)
        } else {
            tpc_sp<0, 0, 0>(s_tab + OFF_K0, w1, &hu0, &hv0, A + 0);  // (0,0,0)
            tpc_sp<1, 1, 0>(s_tab + OFF_K2, w2, hu1, hv1, A + 0);    // (1,1,0)
            tpc_sp<1, 1, 1>(s_tab + OFF_K3, w3, hu1, hv1, A + 1);    // (1,1,1)
            tpc_sp<2, 2, 2>(s_tab + OFF_K8, w4, hu2, hv2, A + 4);    // (2,2,2)
        }

        if (uni) {
#pragma unroll
            for (int i = 0; i < 9; i++) TA[i] += A[i];
        } else {
#pragma unroll
            for (int off = 16; off; off >>= 1)
#pragma unroll
                for (int i = 0; i < 9; i++) A[i] += __shfl_xor_sync(0xffffffffu, A[i], off);
            int n = n0 + j;
            if (lane == 0 && n < N) {
                int b = __ldg(batch + n);
                float* r = g_res + (size_t)b * 9;
#pragma unroll
                for (int i = 0; i < 9; i++) atomicAdd(r + i, A[i]);
            }
        }
    }
    if (uni) {
#pragma unroll
        for (int off = 16; off; off >>= 1)
#pragma unroll
            for (int i = 0; i < 9; i++) TA[i] += __shfl_xor_sync(0xffffffffu, TA[i], off);
        if (lane == 0) {
            float* r = g_res + (size_t)bfirst * 9;
#pragma unroll
            for (int i = 0; i < 9; i++) atomicAdd(r + i, TA[i]);
        }
    }
}

// =====================================================================
// Host-side exact constant generation (mirrors reference numpy code)
// =====================================================================
static double factd(int n) { double r = 1.0; for (int i = 2; i <= n; i++) r *= i; return r; }

static double su2_cg(int j1, int m1, int j2, int m2, int j3, int m3) {
    if (m1 + m2 != m3) return 0.0;
    int vmin = std::max(std::max(-j1 + j2 + m3, -j1 + m1), 0);
    int vmax = std::min(std::min(j2 + j3 + m1, j3 - j1 + j2), j3 + m3);
    if (vmax < vmin) return 0.0;
    double C = std::sqrt((2.0 * j3 + 1.0) *
        factd(j3 + j1 - j2) * factd(j3 - j1 + j2) * factd(j1 + j2 - j3) *
        factd(j3 + m3) * factd(j3 - m3) /
        (factd(j1 + j2 + j3 + 1) * factd(j1 - m1) * factd(j1 + m1) *
         factd(j2 - m2) * factd(j2 + m2)));
    double S = 0.0;
    for (int v = vmin; v <= vmax; v++) {
        double sgn = ((v + j2 + m2) & 1) ? -1.0 : 1.0;
        S += sgn * factd(j2 + j3 + m1 - v) * factd(j1 - m1 + v) /
             (factd(v) * factd(j3 - j1 + j2 - v) * factd(j3 + m3 - v) * factd(v + j1 - j2 - m3));
    }
    return C * S;
}

typedef std::complex<double> cd;

static void qmat(int l, cd q[5][5]) {
    for (int a = 0; a < 5; a++)
        for (int b = 0; b < 5; b++) q[a][b] = 0.0;
    const double r = 1.0 / std::sqrt(2.0);
    for (int m = -l; m < 0; m++) {
        q[l + m][l - m] = r;
        q[l + m][l + m] = cd(0.0, -r);
    }
    q[l][l] = 1.0;
    for (int m = 1; m <= l; m++) {
        double s = (m & 1) ? -1.0 : 1.0;
        q[l + m][l + m] = s * r;
        q[l + m][l - m] = cd(0.0, s * r);
    }
    cd ph = (l == 0) ? cd(1, 0) : (l == 1) ? cd(0, -1) : cd(-1, 0);  // (-i)^l
    for (int a = 0; a <= 2 * l; a++)
        for (int b = 0; b <= 2 * l; b++) q[a][b] *= ph;
}

static void calc_w3j(int l1, int l2, int l3, float* out) {
    int d1 = 2 * l1 + 1, d2 = 2 * l2 + 1, d3 = 2 * l3 + 1;
    cd C[5][5][5];
    for (int a = 0; a < 5; a++)
        for (int b = 0; b < 5; b++)
            for (int c = 0; c < 5; c++) C[a][b][c] = 0.0;
    for (int m1 = -l1; m1 <= l1; m1++)
        for (int m2 = -l2; m2 <= l2; m2++)
            for (int m3 = -l3; m3 <= l3; m3++)
                C[l1 + m1][l2 + m2][l3 + m3] = su2_cg(l1, m1, l2, m2, l3, m3);
    cd q1[5][5], q2[5][5], q3[5][5];
    qmat(l1, q1); qmat(l2, q2); qmat(l3, q3);
    double R[125];
    double nrm = 0.0;
    for (int j = 0; j < d1; j++)
        for (int l = 0; l < d2; l++)
            for (int m = 0; m < d3; m++) {
                cd acc = 0.0;
                for (int i = 0; i < d1; i++)
                    for (int k = 0; k < d2; k++)
                        for (int nn = 0; nn < d3; nn++)
                            acc += q1[i][j] * q2[k][l] * std::conj(q3[nn][m]) * C[i][k][nn];
                double v = acc.real();
                R[(j * d2 + l) * d3 + m] = v;
                nrm += v * v;
            }
    nrm = std::sqrt(nrm);
    for (int t = 0; t < d1 * d2 * d3; t++) out[t] = (float)(R[t] / nrm);
}

extern "C" void kernel_launch(void* const* d_in, const int* in_sizes, int n_in,
                              void* d_out, int out_size) {
    const int*   batch = (const int*)d_in[0];
    const float* xs    = (const float*)d_in[1];
    const float* xsph  = (const float*)d_in[2];
    const float* WU0 = (const float*)d_in[3];
    const float* WU1 = (const float*)d_in[4];
    const float* WU2 = (const float*)d_in[5];
    const float* WV0 = (const float*)d_in[6];
    const float* WV1 = (const float*)d_in[7];
    const float* WV2 = (const float*)d_in[8];
    const float* Wg1 = (const float*)d_in[9];
    const float* bg1 = (const float*)d_in[10];
    const float* Wg2 = (const float*)d_in[11];
    const float* bg2 = (const float*)d_in[12];
    const float* Wp0 = (const float*)d_in[13];
    const float* Wp1 = (const float*)d_in[14];
    const float* Wp2 = (const float*)d_in[15];
    const int N = in_sizes[0];
    const int G = out_size / 9;

    // ---- build constants (deterministic, recomputed every call) ----
    TPParams P;
    const int ins[9][3] = {{0,0,0},{0,2,2},{1,1,0},{1,1,1},{1,1,2},
                           {2,0,2},{2,2,0},{2,2,1},{2,2,2}};
    const int lenl[3] = {3, 2, 4};  // #instructions per output l
    int off = 0;
    for (int k = 0; k < 9; k++) {
        int l1 = ins[k][0], l2 = ins[k][1], l3 = ins[k][2];
        calc_w3j(l1, l2, l3, P.tab + off);
        off += (2 * l1 + 1) * (2 * l2 + 1) * (2 * l3 + 1);
        P.ck[k] = (float)(std::sqrt((2.0 * l3 + 1.0) / 16.0) / std::sqrt((double)lenl[l3]));
    }

    FinParams F;
    {
        float w110[9], w111[27], w112[45];
        calc_w3j(1, 1, 0, w110);
        calc_w3j(1, 1, 1, w111);
        calc_w3j(1, 1, 2, w112);
        double Q[9][3][3];
        for (int i = 0; i < 3; i++)
            for (int j = 0; j < 3; j++) {
                Q[0][i][j] = w110[(i * 3 + j)];
                for (int m = 0; m < 3; m++)
                    Q[1 + m][i][j] = std::sqrt(3.0) * w111[(i * 3 + j) * 3 + m];
                for (int m = 0; m < 5; m++)
                    Q[4 + m][i][j] = std::sqrt(5.0) * w112[(i * 3 + j) * 5 + m];
            }
        const int CART[3] = {2, 0, 1};
        for (int k = 0; k < 9; k++)
            for (int a = 0; a < 3; a++)
                for (int b = 0; b < 3; b++)
                    F.M[k * 9 + a * 3 + b] = (float)Q[k][CART[a]][CART[b]];
    }

    const int smem_bytes = (372 + NPB * NS) * sizeof(float);  // 40400
    cudaFuncSetAttribute(tp_main, cudaFuncAttributeMaxDynamicSharedMemorySize, smem_bytes);

    prep_kernel<<<(G * 9 + 255) / 256, 256>>>(WU0, WU1, WU2, WV0, WV1, WV2, Wg1, Wg2, G * 9);
    tp_main<<<(N + NPB - 1) / NPB, TPB, smem_bytes>>>(
        batch, xs, xsph, bg1, Wg2, bg2, Wp0, Wp1, Wp2, N, P);
    fin_kernel<<<(G * 9 + 255) / 256, 256>>>((float*)d_out, G, F);
}

// round 16
// speedup vs baseline: 1.1063x; 1.1063x over previous
#include <cuda_runtime.h>
#include <cmath>
#include <complex>
#include <algorithm>

// ---------------- device scratch (static; no allocation allowed) ----------------
__device__ float  g_res[262144];    // segment sums res_sph [G*9], zeroed per launch
__device__ float4 g_W0q[32 * 32];   // packed irrep-0 weights: [u/4][lane] = rows (u..u+3)
__device__ float4 g_W1q[16 * 32];   // packed irrep-1 weights
__device__ float4 g_W2q[8 * 32];    // packed irrep-2 weights
__device__ float4 g_Wg1p[64 * 32];  // packed gate1: [i/2][lane] = (W[i][2l],W[i][2l+1],W[i+1][2l],W[i+1][2l+1])
__device__ float2 g_We[32 * 16];    // packed gate2 tail col: [i/2][c] = (Wg2[i][128+c], Wg2[i+1][128+c])

// ---------------- param structs (host-computed constants) ----------------
struct TPParams {
    float tab[357];   // dense W3J tables, packed in INS order
    float ck[9];      // sqrt((2*l3+1)/16)/sqrt(len_l3) per instruction
};
struct FinParams {
    float M[81];      // M[k*9 + a*3 + b] = Q_COB[k][CART[a]][CART[b]]
};

// table offsets (must match host packing order)
#define OFF_K0 0
#define OFF_K1 1
#define OFF_K2 26
#define OFF_K3 35
#define OFF_K4 62
#define OFF_K5 107
#define OFF_K6 132
#define OFF_K7 157
#define OFF_K8 232

#define NB   3      // nodes per warp
#define WPB  8      // warps per block (256 threads -> 3 blocks/SM = 24 warps)
#define TPB  (WPB*32)
#define NPB  (NB*WPB)
#define NS   608    // floats of scratch per node (overlaid, h in registers)

// per-node scratch layout (floats):
//  [0,128)   x_scalar      (silu hidden overlays [0,64) after gate1)
//  [128,256) p0            (w[144] overlays [128,272) after irreps+gate1)
//  [256,448) p1 transposed [3][64]
//  [448,608) p2 transposed [5][32]
#define O_W   128
#define O_P0  128
#define O_P1  256
#define O_P2  448

// ---------------- prep: zero segments + build packed weights ----------------
__global__ void prep_kernel(const float* __restrict__ WU0, const float* __restrict__ WU1,
                            const float* __restrict__ WU2, const float* __restrict__ WV0,
                            const float* __restrict__ WV1, const float* __restrict__ WV2,
                            const float* __restrict__ Wg1, const float* __restrict__ Wg2,
                            int g9) {
    int t = blockIdx.x * blockDim.x + threadIdx.x;
    if (t < g9) g_res[t] = 0.f;
    if (t < 32 * 32) {  // irrep-0: rows 4k..4k+3, column c
        int k = t >> 5, c = t & 31;
        float w[4];
#pragma unroll
        for (int r = 0; r < 4; r++)
            w[r] = (c < 16) ? WU0[(4 * k + r) * 16 + c] : WV0[(4 * k + r) * 16 + c - 16];
        g_W0q[t] = make_float4(w[0], w[1], w[2], w[3]);
    }
    if (t < 16 * 32) {
        int k = t >> 5, c = t & 31;
        float w[4];
#pragma unroll
        for (int r = 0; r < 4; r++)
            w[r] = (c < 16) ? WU1[(4 * k + r) * 16 + c] : WV1[(4 * k + r) * 16 + c - 16];
        g_W1q[t] = make_float4(w[0], w[1], w[2], w[3]);
    }
    if (t < 8 * 32) {
        int k = t >> 5, c = t & 31;
        float w[4];
#pragma unroll
        for (int r = 0; r < 4; r++)
            w[r] = (c < 16) ? WU2[(4 * k + r) * 16 + c] : WV2[(4 * k + r) * 16 + c - 16];
        g_W2q[t] = make_float4(w[0], w[1], w[2], w[3]);
    }
    if (t < 64 * 32) {  // gate1 packed: rows 2k,2k+1 x cols 2c,2c+1
        int k = t >> 5, c = t & 31;
        g_Wg1p[t] = make_float4(Wg1[(2 * k) * 64 + 2 * c],     Wg1[(2 * k) * 64 + 2 * c + 1],
                                Wg1[(2 * k + 1) * 64 + 2 * c], Wg1[(2 * k + 1) * 64 + 2 * c + 1]);
    }
    if (t < 32 * 16) {  // gate2 tail col packed: rows 2k,2k+1, col 128+c
        int k = t >> 4, c = t & 15;
        g_We[t] = make_float2(Wg2[(2 * k) * 144 + 128 + c], Wg2[(2 * k + 1) * 144 + 128 + c]);
    }
}

__global__ void fin_kernel(float* __restrict__ out, int G, FinParams F) {
    int t = blockIdx.x * blockDim.x + threadIdx.x;
    if (t >= G * 9) return;
    int g = t / 9, ab = t - g * 9;
    const float* r = g_res + g * 9;
    float s = 0.f;
#pragma unroll
    for (int k = 0; k < 9; k++) s = fmaf(r[k], F.M[k * 9 + ab], s);
    out[t] = s;
}

// ---------------- real-basis W3J sparsity predicate (compile-time) ----------------
__host__ __device__ constexpr bool w3j_nz(int l1, int i, int l2, int j, int l3, int m) {
    int m1 = i - l1, m2 = j - l2, m3 = m - l3;
    int a1 = m1 < 0 ? -m1 : m1, a2 = m2 < 0 ? -m2 : m2, a3 = m3 < 0 ? -m3 : m3;
    int d = a1 > a2 ? a1 - a2 : a2 - a1;
    bool mag = (a3 == a1 + a2) || (a3 == d);
    int negs = (m1 < 0 ? 1 : 0) + (m2 < 0 ? 1 : 0) + (m3 < 0 ? 1 : 0);
    return mag && ((negs & 1) == ((l1 + l2 + l3) & 1));
}

// ---------------- sparse tensor-product contraction ----------------
template <int L1, int L2, int L3>
__device__ __forceinline__ void tpc_sp(const float* __restrict__ T, float s,
                                       const float* a, const float* b, float* acc) {
    constexpr int D1 = 2 * L1 + 1, D2 = 2 * L2 + 1, D3 = 2 * L3 + 1;
#pragma unroll
    for (int i = 0; i < D1; i++) {
        float as = a[i] * s;
#pragma unroll
        for (int j = 0; j < D2; j++) {
            float ab = as * b[j];
#pragma unroll
            for (int m = 0; m < D3; m++) {
                if (w3j_nz(L1, i, L2, j, L3, m))
                    acc[m] = fmaf(ab, T[(i * D2 + j) * D3 + m], acc[m]);
            }
        }
    }
}

__device__ __forceinline__ float sel4(const float4& v, int t) {
    return (t == 0) ? v.x : (t == 1) ? v.y : (t == 2) ? v.z : v.w;
}

// =====================================================================
// main fused kernel: one warp per NB nodes; h kept in registers
// =====================================================================
__global__ void __launch_bounds__(TPB, 3) tp_main(
    const int* __restrict__ batch,
    const float* __restrict__ xs, const float* __restrict__ xsph,
    const float* __restrict__ bg1,
    const float* __restrict__ Wg2, const float* __restrict__ bg2,
    const float* __restrict__ Wp0, const float* __restrict__ Wp1, const float* __restrict__ Wp2,
    int N, TPParams P) {
    extern __shared__ __align__(16) float dyn[];
    float* s_tab = dyn;          // 357 (+3 pad)
    float* s_cf  = dyn + 360;    // 9 (+3 pad)
    float* scratch = dyn + 372;  // NPB * NS

    for (int i = threadIdx.x; i < 357; i += TPB) s_tab[i] = P.tab[i];
    if (threadIdx.x < 9) {
        int k = threadIdx.x;
        float wp;
        switch (k) {
            case 0: wp = __ldg(Wp0 + 0); break;   // (0,0,0)
            case 1: wp = __ldg(Wp2 + 0); break;   // (0,2,2)
            case 2: wp = __ldg(Wp0 + 1); break;   // (1,1,0)
            case 3: wp = __ldg(Wp1 + 0); break;   // (1,1,1)
            case 4: wp = __ldg(Wp2 + 1); break;   // (1,1,2)
            case 5: wp = __ldg(Wp2 + 2); break;   // (2,0,2)
            case 6: wp = __ldg(Wp0 + 2); break;   // (2,2,0)
            case 7: wp = __ldg(Wp1 + 1); break;   // (2,2,1)
            default: wp = __ldg(Wp2 + 3); break;  // (2,2,2)
        }
        s_cf[k] = P.ck[k] * wp;
    }
    __syncthreads();

    const int warp = threadIdx.x >> 5;
    const int lane = threadIdx.x & 31;
    const int n0 = blockIdx.x * NPB + warp * NB;
    float* S0 = scratch + (size_t)(warp * NB) * NS;
    float* S1 = S0 + NS;
    float* S2 = S0 + 2 * NS;

    // ---- stage node inputs (all float4 LDG; p1/p2 scatter-transposed to shared) ----
#pragma unroll
    for (int j = 0; j < NB; j++) {
        int n = n0 + j;
        float* Sx = S0 + j * NS;
        if (n < N) {
            const float4* xv = (const float4*)(xs + (size_t)n * 128);
            ((float4*)Sx)[lane] = __ldg(xv + lane);
            const float4* p0v = (const float4*)(xsph + (size_t)n * 480);
            ((float4*)(Sx + O_P0))[lane] = __ldg(p0v + lane);
            const float4* prv = (const float4*)(xsph + (size_t)n * 480 + 128);  // 88 float4
#pragma unroll
            for (int r = 0; r < 3; r++) {
                int q = lane + 32 * r;
                if (q < 88) {
                    float4 v = __ldg(prv + q);
                    int base = 4 * q;
#pragma unroll
                    for (int t = 0; t < 4; t++) {
                        int idx = base + t;
                        float val = sel4(v, t);
                        if (idx < 192) {
                            int u = idx / 3, i = idx - 3 * u;
                            Sx[O_P1 + i * 64 + u] = val;
                        } else {
                            int kk = idx - 192;
                            int u = kk / 5, i = kk - 5 * u;
                            Sx[O_P2 + i * 32 + u] = val;
                        }
                    }
                }
            }
        } else {
#pragma unroll
            for (int r = 0; r < 19; r++) {
                int idx = lane + 32 * r;
                if (idx < 608) Sx[idx] = 0.f;
            }
        }
    }
    __syncwarp();

    // ---- irrep linears FIRST: results stay in registers ----
    float h0[NB];
    float h1[NB][3];
    float h2[NB][5];
    {
        {   // l = 0  (inputs at O_P0); packed weights: 4 rows per LDG.128
            float s[NB] = {0.f, 0.f, 0.f};
#pragma unroll 2
            for (int u = 0; u < 128; u += 4) {
                float4 p0 = *(const float4*)(S0 + O_P0 + u);
                float4 p1 = *(const float4*)(S1 + O_P0 + u);
                float4 p2 = *(const float4*)(S2 + O_P0 + u);
                float4 w = __ldg(g_W0q + (u >> 2) * 32 + lane);
                s[0] = fmaf(p0.x, w.x, s[0]); s[0] = fmaf(p0.y, w.y, s[0]);
                s[0] = fmaf(p0.z, w.z, s[0]); s[0] = fmaf(p0.w, w.w, s[0]);
                s[1] = fmaf(p1.x, w.x, s[1]); s[1] = fmaf(p1.y, w.y, s[1]);
                s[1] = fmaf(p1.z, w.z, s[1]); s[1] = fmaf(p1.w, w.w, s[1]);
                s[2] = fmaf(p2.x, w.x, s[2]); s[2] = fmaf(p2.y, w.y, s[2]);
                s[2] = fmaf(p2.z, w.z, s[2]); s[2] = fmaf(p2.w, w.w, s[2]);
            }
            const float C0 = 0.08838834764831845f;  // 1/sqrt(128)
#pragma unroll
            for (int j = 0; j < NB; j++) h0[j] = s[j] * C0;
        }
        {   // l = 1  (inputs transposed [3][64] at O_P1); 4 rows per iter, component-outer
            float b[NB][3];
#pragma unroll
            for (int j = 0; j < NB; j++) { b[j][0] = 0.f; b[j][1] = 0.f; b[j][2] = 0.f; }
#pragma unroll 2
            for (int u = 0; u < 64; u += 4) {
                float4 w = __ldg(g_W1q + (u >> 2) * 32 + lane);
#pragma unroll
                for (int i = 0; i < 3; i++) {
                    float4 q0 = *(const float4*)(S0 + O_P1 + i * 64 + u);
                    float4 q1 = *(const float4*)(S1 + O_P1 + i * 64 + u);
                    float4 q2 = *(const float4*)(S2 + O_P1 + i * 64 + u);
                    b[0][i] = fmaf(q0.x, w.x, b[0][i]); b[0][i] = fmaf(q0.y, w.y, b[0][i]);
                    b[0][i] = fmaf(q0.z, w.z, b[0][i]); b[0][i] = fmaf(q0.w, w.w, b[0][i]);
                    b[1][i] = fmaf(q1.x, w.x, b[1][i]); b[1][i] = fmaf(q1.y, w.y, b[1][i]);
                    b[1][i] = fmaf(q1.z, w.z, b[1][i]); b[1][i] = fmaf(q1.w, w.w, b[1][i]);
                    b[2][i] = fmaf(q2.x, w.x, b[2][i]); b[2][i] = fmaf(q2.y, w.y, b[2][i]);
                    b[2][i] = fmaf(q2.z, w.z, b[2][i]); b[2][i] = fmaf(q2.w, w.w, b[2][i]);
                }
            }
#pragma unroll
            for (int j = 0; j < NB; j++)
#pragma unroll
                for (int i = 0; i < 3; i++) h1[j][i] = b[j][i] * 0.125f;
        }
        {   // l = 2  (inputs transposed [5][32] at O_P2); 4 rows per iter, component-outer
            float d[NB][5];
#pragma unroll
            for (int j = 0; j < NB; j++)
#pragma unroll
                for (int i = 0; i < 5; i++) d[j][i] = 0.f;
#pragma unroll 2
            for (int u = 0; u < 32; u += 4) {
                float4 w = __ldg(g_W2q + (u >> 2) * 32 + lane);
#pragma unroll
                for (int i = 0; i < 5; i++) {
                    float4 r0 = *(const float4*)(S0 + O_P2 + i * 32 + u);
                    float4 r1 = *(const float4*)(S1 + O_P2 + i * 32 + u);
                    float4 r2 = *(const float4*)(S2 + O_P2 + i * 32 + u);
                    d[0][i] = fmaf(r0.x, w.x, d[0][i]); d[0][i] = fmaf(r0.y, w.y, d[0][i]);
                    d[0][i] = fmaf(r0.z, w.z, d[0][i]); d[0][i] = fmaf(r0.w, w.w, d[0][i]);
                    d[1][i] = fmaf(r1.x, w.x, d[1][i]); d[1][i] = fmaf(r1.y, w.y, d[1][i]);
                    d[1][i] = fmaf(r1.z, w.z, d[1][i]); d[1][i] = fmaf(r1.w, w.w, d[1][i]);
                    d[2][i] = fmaf(r2.x, w.x, d[2][i]); d[2][i] = fmaf(r2.y, w.y, d[2][i]);
                    d[2][i] = fmaf(r2.z, w.z, d[2][i]); d[2][i] = fmaf(r2.w, w.w, d[2][i]);
                }
            }
            const float C2 = 0.17677669529663687f;  // 1/sqrt(32)
#pragma unroll
            for (int j = 0; j < NB; j++)
#pragma unroll
                for (int i = 0; i < 5; i++) h2[j][i] = d[j][i] * C2;
        }
    }
    __syncwarp();

    // ---- gate layer 1: hidden = silu(x @ Wg1 + bg1); packed weights (2 rows/LDG.128) ----
    {
        float b0 = __ldg(bg1 + 2 * lane), b1 = __ldg(bg1 + 2 * lane + 1);
        float a00 = b0, a01 = b1, a10 = b0, a11 = b1, a20 = b0, a21 = b1;
#pragma unroll 2
        for (int i = 0; i < 128; i += 4) {
            float4 x0 = *(const float4*)(S0 + i);
            float4 x1 = *(const float4*)(S1 + i);
            float4 x2 = *(const float4*)(S2 + i);
            float4 wa = __ldg(g_Wg1p + (i >> 1) * 32 + lane);        // rows i, i+1
            float4 wb = __ldg(g_Wg1p + ((i >> 1) + 1) * 32 + lane);  // rows i+2, i+3
            a00 = fmaf(x0.x, wa.x, a00); a01 = fmaf(x0.x, wa.y, a01);
            a00 = fmaf(x0.y, wa.z, a00); a01 = fmaf(x0.y, wa.w, a01);
            a00 = fmaf(x0.z, wb.x, a00); a01 = fmaf(x0.z, wb.y, a01);
            a00 = fmaf(x0.w, wb.z, a00); a01 = fmaf(x0.w, wb.w, a01);
            a10 = fmaf(x1.x, wa.x, a10); a11 = fmaf(x1.x, wa.y, a11);
            a10 = fmaf(x1.y, wa.z, a10); a11 = fmaf(x1.y, wa.w, a11);
            a10 = fmaf(x1.z, wb.x, a10); a11 = fmaf(x1.z, wb.y, a11);
            a10 = fmaf(x1.w, wb.z, a10); a11 = fmaf(x1.w, wb.w, a11);
            a20 = fmaf(x2.x, wa.x, a20); a21 = fmaf(x2.x, wa.y, a21);
            a20 = fmaf(x2.y, wa.z, a20); a21 = fmaf(x2.y, wa.w, a21);
            a20 = fmaf(x2.z, wb.x, a20); a21 = fmaf(x2.z, wb.y, a21);
            a20 = fmaf(x2.w, wb.z, a20); a21 = fmaf(x2.w, wb.w, a21);
        }
        S0[2 * lane] = a00 / (1.f + __expf(-a00));
        S0[2 * lane + 1] = a01 / (1.f + __expf(-a01));
        S1[2 * lane] = a10 / (1.f + __expf(-a10));
        S1[2 * lane + 1] = a11 / (1.f + __expf(-a11));
        S2[2 * lane] = a20 / (1.f + __expf(-a20));
        S2[2 * lane + 1] = a21 / (1.f + __expf(-a21));
    }
    __syncwarp();

    // ---- gate layer 2: w = hidden @ Wg2 + bg2; w -> [128,272) (p dead) ----
    {
        float c0[4], c1[4], c2[4];
#pragma unroll
        for (int t = 0; t < 4; t++) {
            float b = __ldg(bg2 + 4 * lane + t);
            c0[t] = b; c1[t] = b; c2[t] = b;
        }
        float eb = __ldg(bg2 + 128 + (lane & 15));
        float e0 = eb, e1 = eb, e2 = eb;
#pragma unroll 4
        for (int i = 0; i < 64; i += 2) {
            float2 g0 = *(const float2*)(S0 + i);
            float2 g1 = *(const float2*)(S1 + i);
            float2 g2 = *(const float2*)(S2 + i);
            float2 wep = __ldg(g_We + (i >> 1) * 16 + (lane & 15));  // tail col rows i, i+1
#pragma unroll
            for (int t = 0; t < 2; t++) {
                const float* wrow = Wg2 + (i + t) * 144;
                float4 wv = __ldg((const float4*)wrow + lane);
                float we = t ? wep.y : wep.x;
                float v0 = t ? g0.y : g0.x;
                float v1 = t ? g1.y : g1.x;
                float v2 = t ? g2.y : g2.x;
                c0[0] = fmaf(v0, wv.x, c0[0]); c0[1] = fmaf(v0, wv.y, c0[1]);
                c0[2] = fmaf(v0, wv.z, c0[2]); c0[3] = fmaf(v0, wv.w, c0[3]);
                c1[0] = fmaf(v1, wv.x, c1[0]); c1[1] = fmaf(v1, wv.y, c1[1]);
                c1[2] = fmaf(v1, wv.z, c1[2]); c1[3] = fmaf(v1, wv.w, c1[3]);
                c2[0] = fmaf(v2, wv.x, c2[0]); c2[1] = fmaf(v2, wv.y, c2[1]);
                c2[2] = fmaf(v2, wv.z, c2[2]); c2[3] = fmaf(v2, wv.w, c2[3]);
                e0 = fmaf(v0, we, e0); e1 = fmaf(v1, we, e1); e2 = fmaf(v2, we, e2);
            }
        }
#pragma unroll
        for (int t = 0; t < 4; t++) {
            S0[O_W + 4 * lane + t] = c0[t];
            S1[O_W + 4 * lane + t] = c1[t];
            S2[O_W + 4 * lane + t] = c2[t];
        }
        if (lane < 16) {
            S0[O_W + 128 + lane] = e0;
            S1[O_W + 128 + lane] = e1;
            S2[O_W + 128 + lane] = e2;
        }
    }
    __syncwarp();

    // ---- tensor product per node; h via shfl; batch-uniform merged reduction ----
    const int u = lane & 15, half = lane >> 4;
    int bfirst = __ldg(batch + (n0 < N ? n0 : N - 1));
    bool uni = (n0 + NB <= N) && (__ldg(batch + n0 + NB - 1) == bfirst);

    float TA[9] = {0, 0, 0, 0, 0, 0, 0, 0, 0};
#pragma unroll 1
    for (int j = 0; j < NB; j++) {
        const float* Sw = S0 + j * NS + O_W;
        // hoist per-node gate weights (LDS) BEFORE the serial shfl chain so
        // the 29-cyc LDS latency overlaps the shfl exchanges
        float w1, w2, w3, w4, w5;
        if (half == 0) {
            w1 = Sw[16 + u] * s_cf[1];
            w2 = Sw[64 + u] * s_cf[4];
            w3 = Sw[80 + u] * s_cf[5];
            w4 = Sw[96 + u] * s_cf[6];
            w5 = Sw[112 + u] * s_cf[7];
        } else {
            w1 = Sw[u] * s_cf[0];
            w2 = Sw[32 + u] * s_cf[2];
            w3 = Sw[48 + u] * s_cf[3];
            w4 = Sw[128 + u] * s_cf[8];
            w5 = 0.f;
        }

        float own[9], par[9];
        own[0] = h0[j];
#pragma unroll
        for (int i = 0; i < 3; i++) own[1 + i] = h1[j][i];
#pragma unroll
        for (int i = 0; i < 5; i++) own[4 + i] = h2[j][i];
#pragma unroll
        for (int i = 0; i < 9; i++) par[i] = __shfl_xor_sync(0xffffffffu, own[i], 16);
        float hu0 = half ? par[0] : own[0];
        float hv0 = half ? own[0] : par[0];
        float hu1[3], hv1[3], hu2[5], hv2[5];
#pragma unroll
        for (int i = 0; i < 3; i++) {
            hu1[i] = half ? par[1 + i] : own[1 + i];
            hv1[i] = half ? own[1 + i] : par[1 + i];
        }
#pragma unroll
        for (int i = 0; i < 5; i++) {
            hu2[i] = half ? par[4 + i] : own[4 + i];
            hv2[i] = half ? own[4 + i] : par[4 + i];
        }

        float A[9] = {0, 0, 0, 0, 0, 0, 0, 0, 0};
        if (half == 0) {
            tpc_sp<0, 2, 2>(s_tab + OFF_K1, w1, &hu0, hv2, A + 4);   // (0,2,2)
            tpc_sp<1, 1, 2>(s_tab + OFF_K4, w2, hu1, hv1, A + 4);    // (1,1,2)
            tpc_sp<2, 0, 2>(s_tab + OFF_K5, w3, hu2, &hv0, A + 4);   // (2,0,2)
            tpc_sp<2, 2, 0>(s_tab + OFF_K6, w4, hu2, hv2, A + 0);    // (2,2,0)
            tpc_sp<2, 2, 1>(s_tab + OFF_K7, w5, hu2, hv2, A + 1);    // (2,2,1)
        } else {
            tpc_sp<0, 0, 0>(s_tab + OFF_K0, w1, &hu0, &hv0, A + 0);  // (0,0,0)
            tpc_sp<1, 1, 0>(s_tab + OFF_K2, w2, hu1, hv1, A + 0);    // (1,1,0)
            tpc_sp<1, 1, 1>(s_tab + OFF_K3, w3, hu1, hv1, A + 1);    // (1,1,1)
            tpc_sp<2, 2, 2>(s_tab + OFF_K8, w4, hu2, hv2, A + 4);    // (2,2,2)
        }

        if (uni) {
#pragma unroll
            for (int i = 0; i < 9; i++) TA[i] += A[i];
        } else {
#pragma unroll
            for (int off = 16; off; off >>= 1)
#pragma unroll
                for (int i = 0; i < 9; i++) A[i] += __shfl_xor_sync(0xffffffffu, A[i], off);
            int n = n0 + j;
            if (lane == 0 && n < N) {
                int b = __ldg(batch + n);
                float* r = g_res + (size_t)b * 9;
#pragma unroll
                for (int i = 0; i < 9; i++) atomicAdd(r + i, A[i]);
            }
        }
    }
    if (uni) {
#pragma unroll
        for (int off = 16; off; off >>= 1)
#pragma unroll
            for (int i = 0; i < 9; i++) TA[i] += __shfl_xor_sync(0xffffffffu, TA[i], off);
        if (lane == 0) {
            float* r = g_res + (size_t)bfirst * 9;
#pragma unroll
            for (int i = 0; i < 9; i++) atomicAdd(r + i, TA[i]);
        }
    }
}

// =====================================================================
// Host-side exact constant generation (mirrors reference numpy code)
// =====================================================================
static double factd(int n) { double r = 1.0; for (int i = 2; i <= n; i++) r *= i; return r; }

static double su2_cg(int j1, int m1, int j2, int m2, int j3, int m3) {
    if (m1 + m2 != m3) return 0.0;
    int vmin = std::max(std::max(-j1 + j2 + m3, -j1 + m1), 0);
    int vmax = std::min(std::min(j2 + j3 + m1, j3 - j1 + j2), j3 + m3);
    if (vmax < vmin) return 0.0;
    double C = std::sqrt((2.0 * j3 + 1.0) *
        factd(j3 + j1 - j2) * factd(j3 - j1 + j2) * factd(j1 + j2 - j3) *
        factd(j3 + m3) * factd(j3 - m3) /
        (factd(j1 + j2 + j3 + 1) * factd(j1 - m1) * factd(j1 + m1) *
         factd(j2 - m2) * factd(j2 + m2)));
    double S = 0.0;
    for (int v = vmin; v <= vmax; v++) {
        double sgn = ((v + j2 + m2) & 1) ? -1.0 : 1.0;
        S += sgn * factd(j2 + j3 + m1 - v) * factd(j1 - m1 + v) /
             (factd(v) * factd(j3 - j1 + j2 - v) * factd(j3 + m3 - v) * factd(v + j1 - j2 - m3));
    }
    return C * S;
}

typedef std::complex<double> cd;

static void qmat(int l, cd q[5][5]) {
    for (int a = 0; a < 5; a++)
        for (int b = 0; b < 5; b++) q[a][b] = 0.0;
    const double r = 1.0 / std::sqrt(2.0);
    for (int m = -l; m < 0; m++) {
        q[l + m][l - m] = r;
        q[l + m][l + m] = cd(0.0, -r);
    }
    q[l][l] = 1.0;
    for (int m = 1; m <= l; m++) {
        double s = (m & 1) ? -1.0 : 1.0;
        q[l + m][l + m] = s * r;
        q[l + m][l - m] = cd(0.0, s * r);
    }
    cd ph = (l == 0) ? cd(1, 0) : (l == 1) ? cd(0, -1) : cd(-1, 0);  // (-i)^l
    for (int a = 0; a <= 2 * l; a++)
        for (int b = 0; b <= 2 * l; b++) q[a][b] *= ph;
}

static void calc_w3j(int l1, int l2, int l3, float* out) {
    int d1 = 2 * l1 + 1, d2 = 2 * l2 + 1, d3 = 2 * l3 + 1;
    cd C[5][5][5];
    for (int a = 0; a < 5; a++)
        for (int b = 0; b < 5; b++)
            for (int c = 0; c < 5; c++) C[a][b][c] = 0.0;
    for (int m1 = -l1; m1 <= l1; m1++)
        for (int m2 = -l2; m2 <= l2; m2++)
            for (int m3 = -l3; m3 <= l3; m3++)
                C[l1 + m1][l2 + m2][l3 + m3] = su2_cg(l1, m1, l2, m2, l3, m3);
    cd q1[5][5], q2[5][5], q3[5][5];
    qmat(l1, q1); qmat(l2, q2); qmat(l3, q3);
    double R[125];
    double nrm = 0.0;
    for (int j = 0; j < d1; j++)
        for (int l = 0; l < d2; l++)
            for (int m = 0; m < d3; m++) {
                cd acc = 0.0;
                for (int i = 0; i < d1; i++)
                    for (int k = 0; k < d2; k++)
                        for (int nn = 0; nn < d3; nn++)
                            acc += q1[i][j] * q2[k][l] * std::conj(q3[nn][m]) * C[i][k][nn];
                double v = acc.real();
                R[(j * d2 + l) * d3 + m] = v;
                nrm += v * v;
            }
    nrm = std::sqrt(nrm);
    for (int t = 0; t < d1 * d2 * d3; t++) out[t] = (float)(R[t] / nrm);
}

extern "C" void kernel_launch(void* const* d_in, const int* in_sizes, int n_in,
                              void* d_out, int out_size) {
    const int*   batch = (const int*)d_in[0];
    const float* xs    = (const float*)d_in[1];
    const float* xsph  = (const float*)d_in[2];
    const float* WU0 = (const float*)d_in[3];
    const float* WU1 = (const float*)d_in[4];
    const float* WU2 = (const float*)d_in[5];
    const float* WV0 = (const float*)d_in[6];
    const float* WV1 = (const float*)d_in[7];
    const float* WV2 = (const float*)d_in[8];
    const float* Wg1 = (const float*)d_in[9];
    const float* bg1 = (const float*)d_in[10];
    const float* Wg2 = (const float*)d_in[11];
    const float* bg2 = (const float*)d_in[12];
    const float* Wp0 = (const float*)d_in[13];
    const float* Wp1 = (const float*)d_in[14];
    const float* Wp2 = (const float*)d_in[15];
    const int N = in_sizes[0];
    const int G = out_size / 9;

    // ---- build constants (deterministic, recomputed every call) ----
    TPParams P;
    const int ins[9][3] = {{0,0,0},{0,2,2},{1,1,0},{1,1,1},{1,1,2},
                           {2,0,2},{2,2,0},{2,2,1},{2,2,2}};
    const int lenl[3] = {3, 2, 4};  // #instructions per output l
    int off = 0;
    for (int k = 0; k < 9; k++) {
        int l1 = ins[k][0], l2 = ins[k][1], l3 = ins[k][2];
        calc_w3j(l1, l2, l3, P.tab + off);
        off += (2 * l1 + 1) * (2 * l2 + 1) * (2 * l3 + 1);
        P.ck[k] = (float)(std::sqrt((2.0 * l3 + 1.0) / 16.0) / std::sqrt((double)lenl[l3]));
    }

    FinParams F;
    {
        float w110[9], w111[27], w112[45];
        calc_w3j(1, 1, 0, w110);
        calc_w3j(1, 1, 1, w111);
        calc_w3j(1, 1, 2, w112);
        double Q[9][3][3];
        for (int i = 0; i < 3; i++)
            for (int j = 0; j < 3; j++) {
                Q[0][i][j] = w110[(i * 3 + j)];
                for (int m = 0; m < 3; m++)
                    Q[1 + m][i][j] = std::sqrt(3.0) * w111[(i * 3 + j) * 3 + m];
                for (int m = 0; m < 5; m++)
                    Q[4 + m][i][j] = std::sqrt(5.0) * w112[(i * 3 + j) * 5 + m];
            }
        const int CART[3] = {2, 0, 1};
        for (int k = 0; k < 9; k++)
            for (int a = 0; a < 3; a++)
                for (int b = 0; b < 3; b++)
                    F.M[k * 9 + a * 3 + b] = (float)Q[k][CART[a]][CART[b]];
    }

    const int smem_bytes = (372 + NPB * NS) * sizeof(float);  // 59856
    cudaFuncSetAttribute(tp_main, cudaFuncAttributeMaxDynamicSharedMemorySize, smem_bytes);

    prep_kernel<<<(G * 9 + 255) / 256, 256>>>(WU0, WU1, WU2, WV0, WV1, WV2, Wg1, Wg2, G * 9);
    tp_main<<<(N + NPB - 1) / NPB, TPB, smem_bytes>>>(
        batch, xs, xsph, bg1, Wg2, bg2, Wp0, Wp1, Wp2, N, P);
    fin_kernel<<<(G * 9 + 255) / 256, 256>>>((float*)d_out, G, F);
}

// round 17
// speedup vs baseline: 1.1084x; 1.0019x over previous
#include <cuda_runtime.h>
#include <cmath>
#include <complex>
#include <algorithm>

// ---------------- device scratch (static; no allocation allowed) ----------------
__device__ float  g_res[262144];    // segment sums res_sph [G*9], zeroed per launch
__device__ float4 g_W0q[32 * 32];   // packed irrep-0 weights: [u/4][lane] = rows (u..u+3)
__device__ float4 g_W1q[16 * 32];   // packed irrep-1 weights
__device__ float4 g_W2q[8 * 32];    // packed irrep-2 weights
__device__ float4 g_Wg1p[64 * 32];  // packed gate1: [i/2][lane] = (W[i][2l],W[i][2l+1],W[i+1][2l],W[i+1][2l+1])
__device__ float2 g_We[32 * 16];    // packed gate2 tail col: [i/2][c] = (Wg2[i][128+c], Wg2[i+1][128+c])

// ---------------- param structs (host-computed constants) ----------------
struct TPParams {
    float tab[357];   // dense W3J tables, packed in INS order
    float ck[9];      // sqrt((2*l3+1)/16)/sqrt(len_l3) per instruction
};
struct FinParams {
    float M[81];      // M[k*9 + a*3 + b] = Q_COB[k][CART[a]][CART[b]]
};

// table offsets (must match host packing order)
#define OFF_K0 0
#define OFF_K1 1
#define OFF_K2 26
#define OFF_K3 35
#define OFF_K4 62
#define OFF_K5 107
#define OFF_K6 132
#define OFF_K7 157
#define OFF_K8 232

#define NB   3      // nodes per warp
#define WPB  8      // warps per block (256 threads -> 3 blocks/SM = 24 warps)
#define TPB  (WPB*32)
#define NPB  (NB*WPB)
#define NS   608    // floats of scratch per node (overlaid, h in registers)

// per-node scratch layout (floats):
//  [0,128)   x_scalar      (silu hidden overlays [0,64) after gate1)
//  [128,256) p0            (w[144] overlays [128,272) after irreps+gate1)
//  [256,448) p1 transposed [3][64]
//  [448,608) p2 transposed [5][32]
#define O_W   128
#define O_P0  128
#define O_P1  256
#define O_P2  448

// ---------------- prep: zero segments + build packed weights ----------------
__global__ void prep_kernel(const float* __restrict__ WU0, const float* __restrict__ WU1,
                            const float* __restrict__ WU2, const float* __restrict__ WV0,
                            const float* __restrict__ WV1, const float* __restrict__ WV2,
                            const float* __restrict__ Wg1, const float* __restrict__ Wg2,
                            int g9) {
    int t = blockIdx.x * blockDim.x + threadIdx.x;
    if (t < g9) g_res[t] = 0.f;
    if (t < 32 * 32) {  // irrep-0: rows 4k..4k+3, column c
        int k = t >> 5, c = t & 31;
        float w[4];
#pragma unroll
        for (int r = 0; r < 4; r++)
            w[r] = (c < 16) ? WU0[(4 * k + r) * 16 + c] : WV0[(4 * k + r) * 16 + c - 16];
        g_W0q[t] = make_float4(w[0], w[1], w[2], w[3]);
    }
    if (t < 16 * 32) {
        int k = t >> 5, c = t & 31;
        float w[4];
#pragma unroll
        for (int r = 0; r < 4; r++)
            w[r] = (c < 16) ? WU1[(4 * k + r) * 16 + c] : WV1[(4 * k + r) * 16 + c - 16];
        g_W1q[t] = make_float4(w[0], w[1], w[2], w[3]);
    }
    if (t < 8 * 32) {
        int k = t >> 5, c = t & 31;
        float w[4];
#pragma unroll
        for (int r = 0; r < 4; r++)
            w[r] = (c < 16) ? WU2[(4 * k + r) * 16 + c] : WV2[(4 * k + r) * 16 + c - 16];
        g_W2q[t] = make_float4(w[0], w[1], w[2], w[3]);
    }
    if (t < 64 * 32) {  // gate1 packed: rows 2k,2k+1 x cols 2c,2c+1
        int k = t >> 5, c = t & 31;
        g_Wg1p[t] = make_float4(Wg1[(2 * k) * 64 + 2 * c],     Wg1[(2 * k) * 64 + 2 * c + 1],
                                Wg1[(2 * k + 1) * 64 + 2 * c], Wg1[(2 * k + 1) * 64 + 2 * c + 1]);
    }
    if (t < 32 * 16) {  // gate2 tail col packed: rows 2k,2k+1, col 128+c
        int k = t >> 4, c = t & 15;
        g_We[t] = make_float2(Wg2[(2 * k) * 144 + 128 + c], Wg2[(2 * k + 1) * 144 + 128 + c]);
    }
}

__global__ void fin_kernel(float* __restrict__ out, int G, FinParams F) {
    int t = blockIdx.x * blockDim.x + threadIdx.x;
    if (t >= G * 9) return;
    int g = t / 9, ab = t - g * 9;
    const float* r = g_res + g * 9;
    float s = 0.f;
#pragma unroll
    for (int k = 0; k < 9; k++) s = fmaf(r[k], F.M[k * 9 + ab], s);
    out[t] = s;
}

// ---------------- real-basis W3J sparsity predicate (compile-time) ----------------
__host__ __device__ constexpr bool w3j_nz(int l1, int i, int l2, int j, int l3, int m) {
    int m1 = i - l1, m2 = j - l2, m3 = m - l3;
    int a1 = m1 < 0 ? -m1 : m1, a2 = m2 < 0 ? -m2 : m2, a3 = m3 < 0 ? -m3 : m3;
    int d = a1 > a2 ? a1 - a2 : a2 - a1;
    bool mag = (a3 == a1 + a2) || (a3 == d);
    int negs = (m1 < 0 ? 1 : 0) + (m2 < 0 ? 1 : 0) + (m3 < 0 ? 1 : 0);
    return mag && ((negs & 1) == ((l1 + l2 + l3) & 1));
}

// ---------------- sparse tensor-product contraction ----------------
template <int L1, int L2, int L3>
__device__ __forceinline__ void tpc_sp(const float* __restrict__ T, float s,
                                       const float* a, const float* b, float* acc) {
    constexpr int D1 = 2 * L1 + 1, D2 = 2 * L2 + 1, D3 = 2 * L3 + 1;
#pragma unroll
    for (int i = 0; i < D1; i++) {
        float as = a[i] * s;
#pragma unroll
        for (int j = 0; j < D2; j++) {
            float ab = as * b[j];
#pragma unroll
            for (int m = 0; m < D3; m++) {
                if (w3j_nz(L1, i, L2, j, L3, m))
                    acc[m] = fmaf(ab, T[(i * D2 + j) * D3 + m], acc[m]);
            }
        }
    }
}

__device__ __forceinline__ float sel4(const float4& v, int t) {
    return (t == 0) ? v.x : (t == 1) ? v.y : (t == 2) ? v.z : v.w;
}

// =====================================================================
// main fused kernel: one warp per NB nodes; h kept in registers
// =====================================================================
__global__ void __launch_bounds__(TPB, 3) tp_main(
    const int* __restrict__ batch,
    const float* __restrict__ xs, const float* __restrict__ xsph,
    const float* __restrict__ bg1,
    const float* __restrict__ Wg2, const float* __restrict__ bg2,
    const float* __restrict__ Wp0, const float* __restrict__ Wp1, const float* __restrict__ Wp2,
    int N, TPParams P) {
    extern __shared__ __align__(16) float dyn[];
    float* s_tab = dyn;          // 357 (+3 pad)
    float* s_cf  = dyn + 360;    // 9 (+3 pad)
    float* scratch = dyn + 372;  // NPB * NS

    for (int i = threadIdx.x; i < 357; i += TPB) s_tab[i] = P.tab[i];
    if (threadIdx.x < 9) {
        int k = threadIdx.x;
        float wp;
        switch (k) {
            case 0: wp = __ldg(Wp0 + 0); break;   // (0,0,0)
            case 1: wp = __ldg(Wp2 + 0); break;   // (0,2,2)
            case 2: wp = __ldg(Wp0 + 1); break;   // (1,1,0)
            case 3: wp = __ldg(Wp1 + 0); break;   // (1,1,1)
            case 4: wp = __ldg(Wp2 + 1); break;   // (1,1,2)
            case 5: wp = __ldg(Wp2 + 2); break;   // (2,0,2)
            case 6: wp = __ldg(Wp0 + 2); break;   // (2,2,0)
            case 7: wp = __ldg(Wp1 + 1); break;   // (2,2,1)
            default: wp = __ldg(Wp2 + 3); break;  // (2,2,2)
        }
        s_cf[k] = P.ck[k] * wp;
    }
    __syncthreads();

    const int warp = threadIdx.x >> 5;
    const int lane = threadIdx.x & 31;
    const int n0 = blockIdx.x * NPB + warp * NB;
    float* S0 = scratch + (size_t)(warp * NB) * NS;
    float* S1 = S0 + NS;
    float* S2 = S0 + 2 * NS;

    // ---- stage node inputs (all float4 LDG; p1/p2 scatter-transposed to shared) ----
#pragma unroll
    for (int j = 0; j < NB; j++) {
        int n = n0 + j;
        float* Sx = S0 + j * NS;
        if (n < N) {
            const float4* xv = (const float4*)(xs + (size_t)n * 128);
            ((float4*)Sx)[lane] = __ldg(xv + lane);
            const float4* p0v = (const float4*)(xsph + (size_t)n * 480);
            ((float4*)(Sx + O_P0))[lane] = __ldg(p0v + lane);
            const float4* prv = (const float4*)(xsph + (size_t)n * 480 + 128);  // 88 float4
#pragma unroll
            for (int r = 0; r < 3; r++) {
                int q = lane + 32 * r;
                if (q < 88) {
                    float4 v = __ldg(prv + q);
                    int base = 4 * q;
#pragma unroll
                    for (int t = 0; t < 4; t++) {
                        int idx = base + t;
                        float val = sel4(v, t);
                        if (idx < 192) {
                            int u = idx / 3, i = idx - 3 * u;
                            Sx[O_P1 + i * 64 + u] = val;
                        } else {
                            int kk = idx - 192;
                            int u = kk / 5, i = kk - 5 * u;
                            Sx[O_P2 + i * 32 + u] = val;
                        }
                    }
                }
            }
        } else {
#pragma unroll
            for (int r = 0; r < 19; r++) {
                int idx = lane + 32 * r;
                if (idx < 608) Sx[idx] = 0.f;
            }
        }
    }
    __syncwarp();

    // ---- irrep linears FIRST: results stay in registers ----
    float h0[NB];
    float h1[NB][3];
    float h2[NB][5];
    {
        {   // l = 0  (inputs at O_P0); packed weights: 4 rows per LDG.128
            float s[NB] = {0.f, 0.f, 0.f};
#pragma unroll 2
            for (int u = 0; u < 128; u += 4) {
                float4 p0 = *(const float4*)(S0 + O_P0 + u);
                float4 p1 = *(const float4*)(S1 + O_P0 + u);
                float4 p2 = *(const float4*)(S2 + O_P0 + u);
                float4 w = __ldg(g_W0q + (u >> 2) * 32 + lane);
                s[0] = fmaf(p0.x, w.x, s[0]); s[0] = fmaf(p0.y, w.y, s[0]);
                s[0] = fmaf(p0.z, w.z, s[0]); s[0] = fmaf(p0.w, w.w, s[0]);
                s[1] = fmaf(p1.x, w.x, s[1]); s[1] = fmaf(p1.y, w.y, s[1]);
                s[1] = fmaf(p1.z, w.z, s[1]); s[1] = fmaf(p1.w, w.w, s[1]);
                s[2] = fmaf(p2.x, w.x, s[2]); s[2] = fmaf(p2.y, w.y, s[2]);
                s[2] = fmaf(p2.z, w.z, s[2]); s[2] = fmaf(p2.w, w.w, s[2]);
            }
            const float C0 = 0.08838834764831845f;  // 1/sqrt(128)
#pragma unroll
            for (int j = 0; j < NB; j++) h0[j] = s[j] * C0;
        }
        {   // l = 1  (inputs transposed [3][64] at O_P1); 4 rows per iter, component-outer
            float b[NB][3];
#pragma unroll
            for (int j = 0; j < NB; j++) { b[j][0] = 0.f; b[j][1] = 0.f; b[j][2] = 0.f; }
#pragma unroll 2
            for (int u = 0; u < 64; u += 4) {
                float4 w = __ldg(g_W1q + (u >> 2) * 32 + lane);
#pragma unroll
                for (int i = 0; i < 3; i++) {
                    float4 q0 = *(const float4*)(S0 + O_P1 + i * 64 + u);
                    float4 q1 = *(const float4*)(S1 + O_P1 + i * 64 + u);
                    float4 q2 = *(const float4*)(S2 + O_P1 + i * 64 + u);
                    b[0][i] = fmaf(q0.x, w.x, b[0][i]); b[0][i] = fmaf(q0.y, w.y, b[0][i]);
                    b[0][i] = fmaf(q0.z, w.z, b[0][i]); b[0][i] = fmaf(q0.w, w.w, b[0][i]);
                    b[1][i] = fmaf(q1.x, w.x, b[1][i]); b[1][i] = fmaf(q1.y, w.y, b[1][i]);
                    b[1][i] = fmaf(q1.z, w.z, b[1][i]); b[1][i] = fmaf(q1.w, w.w, b[1][i]);
                    b[2][i] = fmaf(q2.x, w.x, b[2][i]); b[2][i] = fmaf(q2.y, w.y, b[2][i]);
                    b[2][i] = fmaf(q2.z, w.z, b[2][i]); b[2][i] = fmaf(q2.w, w.w, b[2][i]);
                }
            }
#pragma unroll
            for (int j = 0; j < NB; j++)
#pragma unroll
                for (int i = 0; i < 3; i++) h1[j][i] = b[j][i] * 0.125f;
        }
        {   // l = 2  (inputs transposed [5][32] at O_P2); 4 rows per iter, component-outer
            float d[NB][5];
#pragma unroll
            for (int j = 0; j < NB; j++)
#pragma unroll
                for (int i = 0; i < 5; i++) d[j][i] = 0.f;
#pragma unroll 2
            for (int u = 0; u < 32; u += 4) {
                float4 w = __ldg(g_W2q + (u >> 2) * 32 + lane);
#pragma unroll
                for (int i = 0; i < 5; i++) {
                    float4 r0 = *(const float4*)(S0 + O_P2 + i * 32 + u);
                    float4 r1 = *(const float4*)(S1 + O_P2 + i * 32 + u);
                    float4 r2 = *(const float4*)(S2 + O_P2 + i * 32 + u);
                    d[0][i] = fmaf(r0.x, w.x, d[0][i]); d[0][i] = fmaf(r0.y, w.y, d[0][i]);
                    d[0][i] = fmaf(r0.z, w.z, d[0][i]); d[0][i] = fmaf(r0.w, w.w, d[0][i]);
                    d[1][i] = fmaf(r1.x, w.x, d[1][i]); d[1][i] = fmaf(r1.y, w.y, d[1][i]);
                    d[1][i] = fmaf(r1.z, w.z, d[1][i]); d[1][i] = fmaf(r1.w, w.w, d[1][i]);
                    d[2][i] = fmaf(r2.x, w.x, d[2][i]); d[2][i] = fmaf(r2.y, w.y, d[2][i]);
                    d[2][i] = fmaf(r2.z, w.z, d[2][i]); d[2][i] = fmaf(r2.w, w.w, d[2][i]);
                }
            }
            const float C2 = 0.17677669529663687f;  // 1/sqrt(32)
#pragma unroll
            for (int j = 0; j < NB; j++)
#pragma unroll
                for (int i = 0; i < 5; i++) h2[j][i] = d[j][i] * C2;
        }
    }
    __syncwarp();

    // ---- gate layer 1: hidden = silu(x @ Wg1 + bg1); packed weights (2 rows/LDG.128) ----
    {
        float b0 = __ldg(bg1 + 2 * lane), b1 = __ldg(bg1 + 2 * lane + 1);
        float a00 = b0, a01 = b1, a10 = b0, a11 = b1, a20 = b0, a21 = b1;
#pragma unroll 2
        for (int i = 0; i < 128; i += 4) {
            float4 x0 = *(const float4*)(S0 + i);
            float4 x1 = *(const float4*)(S1 + i);
            float4 x2 = *(const float4*)(S2 + i);
            float4 wa = __ldg(g_Wg1p + (i >> 1) * 32 + lane);        // rows i, i+1
            float4 wb = __ldg(g_Wg1p + ((i >> 1) + 1) * 32 + lane);  // rows i+2, i+3
            a00 = fmaf(x0.x, wa.x, a00); a01 = fmaf(x0.x, wa.y, a01);
            a00 = fmaf(x0.y, wa.z, a00); a01 = fmaf(x0.y, wa.w, a01);
            a00 = fmaf(x0.z, wb.x, a00); a01 = fmaf(x0.z, wb.y, a01);
            a00 = fmaf(x0.w, wb.z, a00); a01 = fmaf(x0.w, wb.w, a01);
            a10 = fmaf(x1.x, wa.x, a10); a11 = fmaf(x1.x, wa.y, a11);
            a10 = fmaf(x1.y, wa.z, a10); a11 = fmaf(x1.y, wa.w, a11);
            a10 = fmaf(x1.z, wb.x, a10); a11 = fmaf(x1.z, wb.y, a11);
            a10 = fmaf(x1.w, wb.z, a10); a11 = fmaf(x1.w, wb.w, a11);
            a20 = fmaf(x2.x, wa.x, a20); a21 = fmaf(x2.x, wa.y, a21);
            a20 = fmaf(x2.y, wa.z, a20); a21 = fmaf(x2.y, wa.w, a21);
            a20 = fmaf(x2.z, wb.x, a20); a21 = fmaf(x2.z, wb.y, a21);
            a20 = fmaf(x2.w, wb.z, a20); a21 = fmaf(x2.w, wb.w, a21);
        }
        S0[2 * lane] = a00 / (1.f + __expf(-a00));
        S0[2 * lane + 1] = a01 / (1.f + __expf(-a01));
        S1[2 * lane] = a10 / (1.f + __expf(-a10));
        S1[2 * lane + 1] = a11 / (1.f + __expf(-a11));
        S2[2 * lane] = a20 / (1.f + __expf(-a20));
        S2[2 * lane + 1] = a21 / (1.f + __expf(-a21));
    }
    __syncwarp();

    // ---- gate layer 2: w = hidden @ Wg2 + bg2; w -> [128,272) (p dead) ----
    {
        float c0[4], c1[4], c2[4];
#pragma unroll
        for (int t = 0; t < 4; t++) {
            float b = __ldg(bg2 + 4 * lane + t);
            c0[t] = b; c1[t] = b; c2[t] = b;
        }
        float eb = __ldg(bg2 + 128 + (lane & 15));
        float e0 = eb, e1 = eb, e2 = eb;
#pragma unroll 4
        for (int i = 0; i < 64; i += 2) {
            float2 g0 = *(const float2*)(S0 + i);
            float2 g1 = *(const float2*)(S1 + i);
            float2 g2 = *(const float2*)(S2 + i);
            float2 wep = __ldg(g_We + (i >> 1) * 16 + (lane & 15));  // tail col rows i, i+1
#pragma unroll
            for (int t = 0; t < 2; t++) {
                const float* wrow = Wg2 + (i + t) * 144;
                float4 wv = __ldg((const float4*)wrow + lane);
                float we = t ? wep.y : wep.x;
                float v0 = t ? g0.y : g0.x;
                float v1 = t ? g1.y : g1.x;
                float v2 = t ? g2.y : g2.x;
                c0[0] = fmaf(v0, wv.x, c0[0]); c0[1] = fmaf(v0, wv.y, c0[1]);
                c0[2] = fmaf(v0, wv.z, c0[2]); c0[3] = fmaf(v0, wv.w, c0[3]);
                c1[0] = fmaf(v1, wv.x, c1[0]); c1[1] = fmaf(v1, wv.y, c1[1]);
                c1[2] = fmaf(v1, wv.z, c1[2]); c1[3] = fmaf(v1, wv.w, c1[3]);
                c2[0] = fmaf(v2, wv.x, c2[0]); c2[1] = fmaf(v2, wv.y, c2[1]);
                c2[2] = fmaf(v2, wv.z, c2[2]); c2[3] = fmaf(v2, wv.w, c2[3]);
                e0 = fmaf(v0, we, e0); e1 = fmaf(v1, we, e1); e2 = fmaf(v2, we, e2);
            }
        }
#pragma unroll
        for (int t = 0; t < 4; t++) {
            S0[O_W + 4 * lane + t] = c0[t];
            S1[O_W + 4 * lane + t] = c1[t];
            S2[O_W + 4 * lane + t] = c2[t];
        }
        if (lane < 16) {
            S0[O_W + 128 + lane] = e0;
            S1[O_W + 128 + lane] = e1;
            S2[O_W + 128 + lane] = e2;
        }
    }
    __syncwarp();

    // ---- tensor product: double-buffered shfl exchange across nodes ----
    const int u = lane & 15, half = lane >> 4;
    int bfirst = __ldg(batch + (n0 < N ? n0 : N - 1));
    bool uni = (n0 + NB <= N) && (__ldg(batch + n0 + NB - 1) == bfirst);

    // par double buffer: prefetch node 0's exchange now
    float parA[9], parB[9];
#pragma unroll
    for (int i = 0; i < 9; i++) {
        float ov = (i == 0) ? h0[0] : (i < 4) ? h1[0][i - 1] : h2[0][i - 4];
        parA[i] = __shfl_xor_sync(0xffffffffu, ov, 16);
    }

    float TA[9] = {0, 0, 0, 0, 0, 0, 0, 0, 0};
#pragma unroll
    for (int j = 0; j < NB; j++) {
        const float* Sw = S0 + j * NS + O_W;
        // hoist per-node gate weights (LDS) early
        float w1, w2, w3, w4, w5;
        if (half == 0) {
            w1 = Sw[16 + u] * s_cf[1];
            w2 = Sw[64 + u] * s_cf[4];
            w3 = Sw[80 + u] * s_cf[5];
            w4 = Sw[96 + u] * s_cf[6];
            w5 = Sw[112 + u] * s_cf[7];
        } else {
            w1 = Sw[u] * s_cf[0];
            w2 = Sw[32 + u] * s_cf[2];
            w3 = Sw[48 + u] * s_cf[3];
            w4 = Sw[128 + u] * s_cf[8];
            w5 = 0.f;
        }

        const float* par = (j & 1) ? parB : parA;
        // prefetch next node's exchange BEFORE this node's FMA block
        if (j + 1 < NB) {
            float* parN = (j & 1) ? parA : parB;
#pragma unroll
            for (int i = 0; i < 9; i++) {
                float ov = (i == 0) ? h0[j + 1] : (i < 4) ? h1[j + 1][i - 1] : h2[j + 1][i - 4];
                parN[i] = __shfl_xor_sync(0xffffffffu, ov, 16);
            }
        }

        float own[9];
        own[0] = h0[j];
#pragma unroll
        for (int i = 0; i < 3; i++) own[1 + i] = h1[j][i];
#pragma unroll
        for (int i = 0; i < 5; i++) own[4 + i] = h2[j][i];

        float hu0 = half ? par[0] : own[0];
        float hv0 = half ? own[0] : par[0];
        float hu1[3], hv1[3], hu2[5], hv2[5];
#pragma unroll
        for (int i = 0; i < 3; i++) {
            hu1[i] = half ? par[1 + i] : own[1 + i];
            hv1[i] = half ? own[1 + i] : par[1 + i];
        }
#pragma unroll
        for (int i = 0; i < 5; i++) {
            hu2[i] = half ? par[4 + i] : own[4 + i];
            hv2[i] = half ? own[4 + i] : par[4 + i];
        }

        if (uni) {
            // accumulate directly into TA (summation order per element preserved)
            if (half == 0) {
                tpc_sp<0, 2, 2>(s_tab + OFF_K1, w1, &hu0, hv2, TA + 4);   // (0,2,2)
                tpc_sp<1, 1, 2>(s_tab + OFF_K4, w2, hu1, hv1, TA + 4);    // (1,1,2)
                tpc_sp<2, 0, 2>(s_tab + OFF_K5, w3, hu2, &hv0, TA + 4);   // (2,0,2)
                tpc_sp<2, 2, 0>(s_tab + OFF_K6, w4, hu2, hv2, TA + 0);    // (2,2,0)
                tpc_sp<2, 2, 1>(s_tab + OFF_K7, w5, hu2, hv2, TA + 1);    // (2,2,1)
            } else {
                tpc_sp<0, 0, 0>(s_tab + OFF_K0, w1, &hu0, &hv0, TA + 0);  // (0,0,0)
                tpc_sp<1, 1, 0>(s_tab + OFF_K2, w2, hu1, hv1, TA + 0);    // (1,1,0)
                tpc_sp<1, 1, 1>(s_tab + OFF_K3, w3, hu1, hv1, TA + 1);    // (1,1,1)
                tpc_sp<2, 2, 2>(s_tab + OFF_K8, w4, hu2, hv2, TA + 4);    // (2,2,2)
            }
        } else {
            float A[9] = {0, 0, 0, 0, 0, 0, 0, 0, 0};
            if (half == 0) {
                tpc_sp<0, 2, 2>(s_tab + OFF_K1, w1, &hu0, hv2, A + 4);
                tpc_sp<1, 1, 2>(s_tab + OFF_K4, w2, hu1, hv1, A + 4);
                tpc_sp<2, 0, 2>(s_tab + OFF_K5, w3, hu2, &hv0, A + 4);
                tpc_sp<2, 2, 0>(s_tab + OFF_K6, w4, hu2, hv2, A + 0);
                tpc_sp<2, 2, 1>(s_tab + OFF_K7, w5, hu2, hv2, A + 1);
            } else {
                tpc_sp<0, 0, 0>(s_tab + OFF_K0, w1, &hu0, &hv0, A + 0);
                tpc_sp<1, 1, 0>(s_tab + OFF_K2, w2, hu1, hv1, A + 0);
                tpc_sp<1, 1, 1>(s_tab + OFF_K3, w3, hu1, hv1, A + 1);
                tpc_sp<2, 2, 2>(s_tab + OFF_K8, w4, hu2, hv2, A + 4);
            }
#pragma unroll
            for (int off = 16; off; off >>= 1)
#pragma unroll
                for (int i = 0; i < 9; i++) A[i] += __shfl_xor_sync(0xffffffffu, A[i], off);
            int n = n0 + j;
            if (lane == 0 && n < N) {
                int b = __ldg(batch + n);
                float* r = g_res + (size_t)b * 9;
#pragma unroll
                for (int i = 0; i < 9; i++) atomicAdd(r + i, A[i]);
            }
        }
    }
    if (uni) {
#pragma unroll
        for (int off = 16; off; off >>= 1)
#pragma unroll
            for (int i = 0; i < 9; i++) TA[i] += __shfl_xor_sync(0xffffffffu, TA[i], off);
        if (lane == 0) {
            float* r = g_res + (size_t)bfirst * 9;
#pragma unroll
            for (int i = 0; i < 9; i++) atomicAdd(r + i, TA[i]);
        }
    }
}

// =====================================================================
// Host-side exact constant generation (mirrors reference numpy code)
// =====================================================================
static double factd(int n) { double r = 1.0; for (int i = 2; i <= n; i++) r *= i; return r; }

static double su2_cg(int j1, int m1, int j2, int m2, int j3, int m3) {
    if (m1 + m2 != m3) return 0.0;
    int vmin = std::max(std::max(-j1 + j2 + m3, -j1 + m1), 0);
    int vmax = std::min(std::min(j2 + j3 + m1, j3 - j1 + j2), j3 + m3);
    if (vmax < vmin) return 0.0;
    double C = std::sqrt((2.0 * j3 + 1.0) *
        factd(j3 + j1 - j2) * factd(j3 - j1 + j2) * factd(j1 + j2 - j3) *
        factd(j3 + m3) * factd(j3 - m3) /
        (factd(j1 + j2 + j3 + 1) * factd(j1 - m1) * factd(j1 + m1) *
         factd(j2 - m2) * factd(j2 + m2)));
    double S = 0.0;
    for (int v = vmin; v <= vmax; v++) {
        double sgn = ((v + j2 + m2) & 1) ? -1.0 : 1.0;
        S += sgn * factd(j2 + j3 + m1 - v) * factd(j1 - m1 + v) /
             (factd(v) * factd(j3 - j1 + j2 - v) * factd(j3 + m3 - v) * factd(v + j1 - j2 - m3));
    }
    return C * S;
}

typedef std::complex<double> cd;

static void qmat(int l, cd q[5][5]) {
    for (int a = 0; a < 5; a++)
        for (int b = 0; b < 5; b++) q[a][b] = 0.0;
    const double r = 1.0 / std::sqrt(2.0);
    for (int m = -l; m < 0; m++) {
        q[l + m][l - m] = r;
        q[l + m][l + m] = cd(0.0, -r);
    }
    q[l][l] = 1.0;
    for (int m = 1; m <= l; m++) {
        double s = (m & 1) ? -1.0 : 1.0;
        q[l + m][l + m] = s * r;
        q[l + m][l - m] = cd(0.0, s * r);
    }
    cd ph = (l == 0) ? cd(1, 0) : (l == 1) ? cd(0, -1) : cd(-1, 0);  // (-i)^l
    for (int a = 0; a <= 2 * l; a++)
        for (int b = 0; b <= 2 * l; b++) q[a][b] *= ph;
}

static void calc_w3j(int l1, int l2, int l3, float* out) {
    int d1 = 2 * l1 + 1, d2 = 2 * l2 + 1, d3 = 2 * l3 + 1;
    cd C[5][5][5];
    for (int a = 0; a < 5; a++)
        for (int b = 0; b < 5; b++)
            for (int c = 0; c < 5; c++) C[a][b][c] = 0.0;
    for (int m1 = -l1; m1 <= l1; m1++)
        for (int m2 = -l2; m2 <= l2; m2++)
            for (int m3 = -l3; m3 <= l3; m3++)
                C[l1 + m1][l2 + m2][l3 + m3] = su2_cg(l1, m1, l2, m2, l3, m3);
    cd q1[5][5], q2[5][5], q3[5][5];
    qmat(l1, q1); qmat(l2, q2); qmat(l3, q3);
    double R[125];
    double nrm = 0.0;
    for (int j = 0; j < d1; j++)
        for (int l = 0; l < d2; l++)
            for (int m = 0; m < d3; m++) {
                cd acc = 0.0;
                for (int i = 0; i < d1; i++)
                    for (int k = 0; k < d2; k++)
                        for (int nn = 0; nn < d3; nn++)
                            acc += q1[i][j] * q2[k][l] * std::conj(q3[nn][m]) * C[i][k][nn];
                double v = acc.real();
                R[(j * d2 + l) * d3 + m] = v;
                nrm += v * v;
            }
    nrm = std::sqrt(nrm);
    for (int t = 0; t < d1 * d2 * d3; t++) out[t] = (float)(R[t] / nrm);
}

extern "C" void kernel_launch(void* const* d_in, const int* in_sizes, int n_in,
                              void* d_out, int out_size) {
    const int*   batch = (const int*)d_in[0];
    const float* xs    = (const float*)d_in[1];
    const float* xsph  = (const float*)d_in[2];
    const float* WU0 = (const float*)d_in[3];
    const float* WU1 = (const float*)d_in[4];
    const float* WU2 = (const float*)d_in[5];
    const float* WV0 = (const float*)d_in[6];
    const float* WV1 = (const float*)d_in[7];
    const float* WV2 = (const float*)d_in[8];
    const float* Wg1 = (const float*)d_in[9];
    const float* bg1 = (const float*)d_in[10];
    const float* Wg2 = (const float*)d_in[11];
    const float* bg2 = (const float*)d_in[12];
    const float* Wp0 = (const float*)d_in[13];
    const float* Wp1 = (const float*)d_in[14];
    const float* Wp2 = (const float*)d_in[15];
    const int N = in_sizes[0];
    const int G = out_size / 9;

    // ---- build constants (deterministic, recomputed every call) ----
    TPParams P;
    const int ins[9][3] = {{0,0,0},{0,2,2},{1,1,0},{1,1,1},{1,1,2},
                           {2,0,2},{2,2,0},{2,2,1},{2,2,2}};
    const int lenl[3] = {3, 2, 4};  // #instructions per output l
    int off = 0;
    for (int k = 0; k < 9; k++) {
        int l1 = ins[k][0], l2 = ins[k][1], l3 = ins[k][2];
        calc_w3j(l1, l2, l3, P.tab + off);
        off += (2 * l1 + 1) * (2 * l2 + 1) * (2 * l3 + 1);
        P.ck[k] = (float)(std::sqrt((2.0 * l3 + 1.0) / 16.0) / std::sqrt((double)lenl[l3]));
    }

    FinParams F;
    {
        float w110[9], w111[27], w112[45];
        calc_w3j(1, 1, 0, w110);
        calc_w3j(1, 1, 1, w111);
        calc_w3j(1, 1, 2, w112);
        double Q[9][3][3];
        for (int i = 0; i < 3; i++)
            for (int j = 0; j < 3; j++) {
                Q[0][i][j] = w110[(i * 3 + j)];
                for (int m = 0; m < 3; m++)
                    Q[1 + m][i][j] = std::sqrt(3.0) * w111[(i * 3 + j) * 3 + m];
                for (int m = 0; m < 5; m++)
                    Q[4 + m][i][j] = std::sqrt(5.0) * w112[(i * 3 + j) * 5 + m];
            }
        const int CART[3] = {2, 0, 1};
        for (int k = 0; k < 9; k++)
            for (int a = 0; a < 3; a++)
                for (int b = 0; b < 3; b++)
                    F.M[k * 9 + a * 3 + b] = (float)Q[k][CART[a]][CART[b]];
    }

    const int smem_bytes = (372 + NPB * NS) * sizeof(float);  // 59856
    cudaFuncSetAttribute(tp_main, cudaFuncAttributeMaxDynamicSharedMemorySize, smem_bytes);

    prep_kernel<<<(G * 9 + 255) / 256, 256>>>(WU0, WU1, WU2, WV0, WV1, WV2, Wg1, Wg2, G * 9);
    tp_main<<<(N + NPB - 1) / NPB, TPB, smem_bytes>>>(
        batch, xs, xsph, bg1, Wg2, bg2, Wp0, Wp1, Wp2, N, P);
    fin_kernel<<<(G * 9 + 255) / 256, 256>>>((float*)d_out, G, F);
}